// round 5
// baseline (speedup 1.0000x reference)
#include <cuda_runtime.h>
#include <math.h>

#define VOCAB   100000
#define EMBED   64
#define SENT    20
#define MEM     50
#define BATCH   32
#define HOPS    3

// Scratch: 4 context tensors [B,M,E] (mA, mC0, mC1, mC2) + final u [B,E]
__device__ float g_m[4][BATCH * MEM * EMBED];   // 1.6 MB
__device__ float g_u[BATCH * EMBED];

// ---------------------------------------------------------------------------
// f32x2 helpers (Blackwell packed fp32 pipe — 2x fp32 FMA throughput)
// ---------------------------------------------------------------------------
__device__ __forceinline__ void fma2(unsigned long long& acc,
                                     unsigned long long a,
                                     unsigned long long b) {
    asm("fma.rn.f32x2 %0, %1, %2, %0;" : "+l"(acc) : "l"(a), "l"(b));
}
__device__ __forceinline__ unsigned long long pack2(float x, float y) {
    unsigned long long r;
    asm("mov.b64 %0, {%1, %2};" : "=l"(r) : "f"(x), "f"(y));
    return r;
}
__device__ __forceinline__ float2 unpack2(unsigned long long v) {
    float2 r;
    asm("mov.b64 {%0, %1}, %2;" : "=f"(r.x), "=f"(r.y) : "l"(v));
    return r;
}

// ---------------------------------------------------------------------------
// Kernel A: gather + position-encode the 4 context tensors.
// Block = 256 threads = 4 table-groups x 64 embed dims; one block per (b,m).
// Indices staged in smem; 20 gather loads per thread fully unrolled (MLP~20).
// ---------------------------------------------------------------------------
__global__ void __launch_bounds__(256) context_kernel(
        const int* __restrict__ stories,
        const float* __restrict__ A,
        const float* __restrict__ C,
        const float* __restrict__ enc) {
    int bm = blockIdx.x;           // 0..1599
    int t  = threadIdx.x >> 6;     // table 0..3
    int e  = threadIdx.x & 63;     // embed dim

    __shared__ int s_idx[SENT];
    if (threadIdx.x < SENT) s_idx[threadIdx.x] = stories[bm * SENT + threadIdx.x];
    __syncthreads();

    const float* tab = (t == 0) ? A : (C + (size_t)(t - 1) * VOCAB * EMBED);

    // Issue all 20 independent gathers first (high MLP), then reduce.
    float vals[SENT];
#pragma unroll
    for (int s = 0; s < SENT; s++)
        vals[s] = __ldg(tab + (size_t)s_idx[s] * EMBED + e);

    float acc = 0.f;
#pragma unroll
    for (int s = 0; s < SENT; s++)
        acc = fmaf(vals[s], enc[s * EMBED + e], acc);

    g_m[t][bm * EMBED + e] = acc;
}

// ---------------------------------------------------------------------------
// Kernel B: query embedding + 3-hop attention. One block (64 thr) per batch.
// Parallel softmax via warp shuffles.
// ---------------------------------------------------------------------------
__global__ void __launch_bounds__(64) hops_kernel(
        const int* __restrict__ queries,
        const float* __restrict__ A,
        const float* __restrict__ enc) {
    int b    = blockIdx.x;
    int tid  = threadIdx.x;        // 0..63
    int lane = tid & 31;
    int wid  = tid >> 5;

    __shared__ float s_u[EMBED];
    __shared__ float s_p[EMBED];   // padded to 64; [MEM..63] zero
    __shared__ float s_red[2];
    __shared__ float s_inv;

    // u0 = sum_s A[q[s]] * enc[s]
    int qidx[SENT];
#pragma unroll
    for (int s = 0; s < SENT; s++) qidx[s] = queries[b * SENT + s];
    float ue = 0.f;
#pragma unroll
    for (int s = 0; s < SENT; s++)
        ue = fmaf(__ldg(A + (size_t)qidx[s] * EMBED + tid), enc[s * EMBED + tid], ue);
    s_u[tid] = ue;
    __syncthreads();

    for (int hop = 0; hop < HOPS; hop++) {
        const float* mX = g_m[hop]     + b * MEM * EMBED;
        const float* cX = g_m[hop + 1] + b * MEM * EMBED;

        // dotted[m] = m[m,:] . u   (threads >= MEM produce -inf)
        float d = -1e30f;
        if (tid < MEM) {
            float acc = 0.f;
#pragma unroll 16
            for (int e = 0; e < EMBED; e++)
                acc = fmaf(mX[tid * EMBED + e], s_u[e], acc);
            d = acc;
        }

        // block max via shuffles
        float w = d;
#pragma unroll
        for (int off = 16; off > 0; off >>= 1)
            w = fmaxf(w, __shfl_xor_sync(0xffffffffu, w, off));
        if (lane == 0) s_red[wid] = w;
        __syncthreads();
        float mx = fmaxf(s_red[0], s_red[1]);

        // parallel exp + block sum
        float p = (tid < MEM) ? __expf(d - mx) : 0.f;
        s_p[tid] = p;
        float sw = p;
#pragma unroll
        for (int off = 16; off > 0; off >>= 1)
            sw += __shfl_xor_sync(0xffffffffu, sw, off);
        if (lane == 0) s_red[wid] = sw;
        __syncthreads();
        if (tid == 0) s_inv = 1.f / (s_red[0] + s_red[1]);
        __syncthreads();

        // o[e] = sum_m probs[m] * c[m,e];  u += o
        float inv = s_inv;
        float o = 0.f;
#pragma unroll 10
        for (int m = 0; m < MEM; m++)
            o = fmaf(s_p[m] * inv, cX[m * EMBED + tid], o);
        float nu = s_u[tid] + o;
        __syncthreads();
        s_u[tid] = nu;
        __syncthreads();
    }
    g_u[b * EMBED + tid] = s_u[tid];
}

// ---------------------------------------------------------------------------
// Kernel C: out[32, V] = u[32,64] @ C2[V,64]^T
// One vocab row per thread; 32 batches packed into 16 u64 accumulators.
// u pre-packed in smem as u64 pairs -> fma2 consumes LDS results directly,
// no per-iteration packing movs. ~70 regs -> 21 warps/SM (fma2 pipe bound).
// ---------------------------------------------------------------------------
__global__ void __launch_bounds__(128) out_gemm(const float* __restrict__ C2,
                                                float* __restrict__ out) {
    __shared__ unsigned long long s_up[EMBED * 16];   // 8 KB: [e][pair i]

    int tid = threadIdx.x;
    for (int idx = tid; idx < EMBED * 16; idx += 128) {
        int e = idx >> 4, i = idx & 15;
        s_up[idx] = pack2(g_u[(2 * i) * EMBED + e], g_u[(2 * i + 1) * EMBED + e]);
    }
    __syncthreads();

    int v = blockIdx.x * 128 + tid;
    if (v >= VOCAB) return;   // no syncs below — safe early-exit

    unsigned long long acc[16];
#pragma unroll
    for (int i = 0; i < 16; i++) acc[i] = 0ull;

    const float4* row = (const float4*)(C2 + (size_t)v * EMBED);

#pragma unroll
    for (int ch = 0; ch < 4; ch++) {
        float4 r[4];
#pragma unroll
        for (int j = 0; j < 4; j++) r[j] = row[ch * 4 + j];
        const float* f = (const float*)r;
#pragma unroll
        for (int e16 = 0; e16 < 16; e16++) {
            int e = ch * 16 + e16;
            unsigned long long bc = pack2(f[e16], f[e16]);
            const unsigned long long* up = s_up + e * 16;
#pragma unroll
            for (int i = 0; i < 16; i++)
                fma2(acc[i], up[i], bc);
        }
    }

#pragma unroll
    for (int i = 0; i < 16; i++) {
        float2 a = unpack2(acc[i]);   // (b=2i @ v, b=2i+1 @ v)
        out[(size_t)(2 * i)     * VOCAB + v] = a.x;
        out[(size_t)(2 * i + 1) * VOCAB + v] = a.y;
    }
}

// ---------------------------------------------------------------------------
extern "C" void kernel_launch(void* const* d_in, const int* in_sizes, int n_in,
                              void* d_out, int out_size) {
    const int*   stories = (const int*)d_in[0];
    const int*   queries = (const int*)d_in[1];
    const float* A       = (const float*)d_in[2];
    const float* C       = (const float*)d_in[3];
    const float* enc     = (const float*)d_in[4];
    float*       out     = (float*)d_out;

    context_kernel<<<BATCH * MEM, 256>>>(stories, A, C, enc);
    hops_kernel<<<BATCH, 64>>>(queries, A, enc);
    out_gemm<<<(VOCAB + 127) / 128, 128>>>(C + (size_t)2 * VOCAB * EMBED, out);
}

// round 7
// speedup vs baseline: 1.1299x; 1.1299x over previous
#include <cuda_runtime.h>
#include <math.h>

#define VOCAB   100000
#define EMBED   64
#define SENT    20
#define MEM     50
#define BATCH   32
#define HOPS    3

// Scratch: 4 context tensors [B,M,E] (mA, mC0, mC1, mC2) + final u [B,E]
__device__ float g_m[4][BATCH * MEM * EMBED];   // 1.6 MB
__device__ float g_u[BATCH * EMBED];

// ---------------------------------------------------------------------------
// f32x2 helpers (Blackwell packed fp32 pipe — 2x fp32 FMA throughput)
// ---------------------------------------------------------------------------
__device__ __forceinline__ void fma2(unsigned long long& acc,
                                     unsigned long long a,
                                     unsigned long long b) {
    asm("fma.rn.f32x2 %0, %1, %2, %0;" : "+l"(acc) : "l"(a), "l"(b));
}
__device__ __forceinline__ unsigned long long pack2(float x, float y) {
    unsigned long long r;
    asm("mov.b64 %0, {%1, %2};" : "=l"(r) : "f"(x), "f"(y));
    return r;
}
__device__ __forceinline__ float2 unpack2(unsigned long long v) {
    float2 r;
    asm("mov.b64 {%0, %1}, %2;" : "=f"(r.x), "=f"(r.y) : "l"(v));
    return r;
}

// ---------------------------------------------------------------------------
// Kernel A: gather + position-encode the 4 context tensors.
// Block = 256 threads = 4 table-groups x 64 embed dims; one block per (b,m).
// (Round-5 version: measured 10.4us, 78% occ — keep.)
// ---------------------------------------------------------------------------
__global__ void __launch_bounds__(256) context_kernel(
        const int* __restrict__ stories,
        const float* __restrict__ A,
        const float* __restrict__ C,
        const float* __restrict__ enc) {
    int bm = blockIdx.x;           // 0..1599
    int t  = threadIdx.x >> 6;     // table 0..3
    int e  = threadIdx.x & 63;     // embed dim

    __shared__ int s_idx[SENT];
    if (threadIdx.x < SENT) s_idx[threadIdx.x] = stories[bm * SENT + threadIdx.x];
    __syncthreads();

    const float* tab = (t == 0) ? A : (C + (size_t)(t - 1) * VOCAB * EMBED);

    // Issue all 20 independent gathers first (high MLP), then reduce.
    float vals[SENT];
#pragma unroll
    for (int s = 0; s < SENT; s++)
        vals[s] = __ldg(tab + (size_t)s_idx[s] * EMBED + e);

    float acc = 0.f;
#pragma unroll
    for (int s = 0; s < SENT; s++)
        acc = fmaf(vals[s], enc[s * EMBED + e], acc);

    g_m[t][bm * EMBED + e] = acc;
}

// ---------------------------------------------------------------------------
// Kernel B: query embedding + 3-hop attention. One block (64 thr) per batch.
// Parallel softmax via warp shuffles.
// ---------------------------------------------------------------------------
__global__ void __launch_bounds__(64) hops_kernel(
        const int* __restrict__ queries,
        const float* __restrict__ A,
        const float* __restrict__ enc) {
    int b    = blockIdx.x;
    int tid  = threadIdx.x;        // 0..63
    int lane = tid & 31;
    int wid  = tid >> 5;

    __shared__ float s_u[EMBED];
    __shared__ float s_p[EMBED];   // padded to 64; [MEM..63] zero
    __shared__ float s_red[2];
    __shared__ float s_inv;

    // u0 = sum_s A[q[s]] * enc[s]
    int qidx[SENT];
#pragma unroll
    for (int s = 0; s < SENT; s++) qidx[s] = queries[b * SENT + s];
    float ue = 0.f;
#pragma unroll
    for (int s = 0; s < SENT; s++)
        ue = fmaf(__ldg(A + (size_t)qidx[s] * EMBED + tid), enc[s * EMBED + tid], ue);
    s_u[tid] = ue;
    __syncthreads();

    for (int hop = 0; hop < HOPS; hop++) {
        const float* mX = g_m[hop]     + b * MEM * EMBED;
        const float* cX = g_m[hop + 1] + b * MEM * EMBED;

        // dotted[m] = m[m,:] . u   (threads >= MEM produce -inf)
        float d = -1e30f;
        if (tid < MEM) {
            float acc = 0.f;
#pragma unroll 16
            for (int e = 0; e < EMBED; e++)
                acc = fmaf(mX[tid * EMBED + e], s_u[e], acc);
            d = acc;
        }

        // block max via shuffles
        float w = d;
#pragma unroll
        for (int off = 16; off > 0; off >>= 1)
            w = fmaxf(w, __shfl_xor_sync(0xffffffffu, w, off));
        if (lane == 0) s_red[wid] = w;
        __syncthreads();
        float mx = fmaxf(s_red[0], s_red[1]);

        // parallel exp + block sum
        float p = (tid < MEM) ? __expf(d - mx) : 0.f;
        s_p[tid] = p;
        float sw = p;
#pragma unroll
        for (int off = 16; off > 0; off >>= 1)
            sw += __shfl_xor_sync(0xffffffffu, sw, off);
        if (lane == 0) s_red[wid] = sw;
        __syncthreads();
        if (tid == 0) s_inv = 1.f / (s_red[0] + s_red[1]);
        __syncthreads();

        // o[e] = sum_m probs[m] * c[m,e];  u += o
        float inv = s_inv;
        float o = 0.f;
#pragma unroll 10
        for (int m = 0; m < MEM; m++)
            o = fmaf(s_p[m] * inv, cX[m * EMBED + tid], o);
        float nu = s_u[tid] + o;
        __syncthreads();
        s_u[tid] = nu;
        __syncthreads();
    }
    g_u[b * EMBED + tid] = s_u[tid];
}

// ---------------------------------------------------------------------------
// Kernel C: out[32, V] = u[32,64] @ C2[V,64]^T
// 2 vocab rows per thread, 32 batches packed into 16+16 u64 accumulators.
// u pre-packed in smem as u64 pairs; loaded as ulonglong2 (LDS.128), each
// LDS feeding 4 fma2 (2 pairs x 2 rows). Inner loop: 8 LDS.128 + 2 packs
// + 32 fma2 per e -> fma2-pipe bound (~5.4us floor), LDS fully hidden.
// ---------------------------------------------------------------------------
__global__ void __launch_bounds__(128) out_gemm(const float* __restrict__ C2,
                                                float* __restrict__ out) {
    __shared__ __align__(16) unsigned long long s_up[EMBED * 16];  // [e][pair i]

    int tid = threadIdx.x;
    for (int idx = tid; idx < EMBED * 16; idx += 128) {
        int e = idx >> 4, i = idx & 15;
        s_up[idx] = pack2(g_u[(2 * i) * EMBED + e], g_u[(2 * i + 1) * EMBED + e]);
    }
    __syncthreads();

    int gid = blockIdx.x * 128 + tid;
    if (gid >= VOCAB / 2) return;   // no syncs below — safe early-exit
    int v0 = gid * 2;

    unsigned long long acc0[16], acc1[16];
#pragma unroll
    for (int i = 0; i < 16; i++) { acc0[i] = 0ull; acc1[i] = 0ull; }

    const float4* row0 = (const float4*)(C2 + (size_t)v0 * EMBED);
    const float4* row1 = row0 + (EMBED / 4);

#pragma unroll
    for (int ch = 0; ch < 4; ch++) {
        float4 r0[4], r1[4];
#pragma unroll
        for (int j = 0; j < 4; j++) { r0[j] = row0[ch * 4 + j]; r1[j] = row1[ch * 4 + j]; }
        const float* f0 = (const float*)r0;
        const float* f1 = (const float*)r1;
#pragma unroll
        for (int e16 = 0; e16 < 16; e16++) {
            int e = ch * 16 + e16;
            unsigned long long bc0 = pack2(f0[e16], f0[e16]);   // row v0 scalar, both lanes
            unsigned long long bc1 = pack2(f1[e16], f1[e16]);   // row v0+1
            const ulonglong2* up2 = (const ulonglong2*)(s_up + e * 16);
#pragma unroll
            for (int j = 0; j < 8; j++) {
                ulonglong2 q = up2[j];             // pairs i=2j, i=2j+1
                fma2(acc0[2 * j],     q.x, bc0);
                fma2(acc0[2 * j + 1], q.y, bc0);
                fma2(acc1[2 * j],     q.x, bc1);
                fma2(acc1[2 * j + 1], q.y, bc1);
            }
        }
    }

    // acc0[i] = (out[2i][v0], out[2i+1][v0]); acc1[i] = same for v0+1.
    // Write float2 (v0, v0+1) per batch row — coalesced across threads.
#pragma unroll
    for (int i = 0; i < 16; i++) {
        float2 a0 = unpack2(acc0[i]);
        float2 a1 = unpack2(acc1[i]);
        *(float2*)(out + (size_t)(2 * i)     * VOCAB + v0) = make_float2(a0.x, a1.x);
        *(float2*)(out + (size_t)(2 * i + 1) * VOCAB + v0) = make_float2(a0.y, a1.y);
    }
}

// ---------------------------------------------------------------------------
extern "C" void kernel_launch(void* const* d_in, const int* in_sizes, int n_in,
                              void* d_out, int out_size) {
    const int*   stories = (const int*)d_in[0];
    const int*   queries = (const int*)d_in[1];
    const float* A       = (const float*)d_in[2];
    const float* C       = (const float*)d_in[3];
    const float* enc     = (const float*)d_in[4];
    float*       out     = (float*)d_out;

    context_kernel<<<BATCH * MEM, 256>>>(stories, A, C, enc);
    hops_kernel<<<BATCH, 64>>>(queries, A, enc);
    out_gemm<<<(VOCAB / 2 + 127) / 128, 128>>>(C + (size_t)2 * VOCAB * EMBED, out);
}